// round 1
// baseline (speedup 1.0000x reference)
#include <cuda_runtime.h>
#include <math.h>

#define B_ 256
#define S_ 128
#define H_ 768
#define A_ 512
#define N_ 10
#define C_ 3
#define K_ 3
#define M_ (B_*S_)   // 32768

// ---------------- scratch (static device globals; no allocation) ----------------
__device__ float g_W2[H_*32];                 // rearranged sem weights, padded 30->32
__device__ float g_sem[(size_t)M_*30];        // semantic linear out, layout j = n*3+c
__device__ float g_vote[(size_t)K_*M_*C_];    // vote (K,M,C) contiguous == h view
__device__ float g_h2[(size_t)M_*H_];         // x + gated capsule output
__device__ float g_a1[(size_t)M_*A_];         // adapter hidden
__device__ float g_gate1[A_];
__device__ float g_gate2[H_];
__device__ float g_gl[H_];
__device__ int   g_t;

// ---------------- scalar decode (handles int32 or float32 encodings) ----------------
__device__ __forceinline__ int decode_int(const void* p){
    int v = *(const int*)p;
    if (v >= -1000000 && v <= 1000000) return v;          // plausible raw int
    return (int)__int_as_float(v);                         // else it was a float bit pattern
}
__device__ __forceinline__ float decode_float(const void* p){
    int v = *(const int*)p;
    if (v >= -1000000 && v <= 1000000) return (float)v;
    return __int_as_float(v);
}

__device__ __forceinline__ float sigmoidf_(float x){ return 1.f/(1.f+expf(-x)); }
__device__ __forceinline__ float gelu_exact(float x){
    return 0.5f*x*(1.f+erff(x*0.70710678118654752f));
}

// ---------------- K0: decode scalars, precompute HAT gates ----------------
__global__ void prep_kernel(const void* tptr, const void* sptr,
                            const float* __restrict__ efc1,
                            const float* __restrict__ efc2,
                            const float* __restrict__ elarger){
    __shared__ int st; __shared__ float ssf;
    if (threadIdx.x == 0){
        int t = decode_int(tptr);
        float sf = decode_float(sptr);
        st = t; ssf = sf; g_t = t;
    }
    __syncthreads();
    int t = st; float sf = ssf;
    int i = threadIdx.x;
    if (i < A_) g_gate1[i] = sigmoidf_(sf*efc1[t*A_+i]);
    if (i < H_){
        g_gate2[i] = sigmoidf_(sf*efc2[t*H_+i]);
        g_gl[i]    = sigmoidf_(sf*elarger[t*H_+i]);
    }
}

// ---------------- K0b: rearrange sem_w (N,H,C) -> W2[h][j], j=n*3+c, padded to 32 ----------------
__global__ void w2_kernel(const float* __restrict__ sem_w){
    int idx = blockIdx.x*blockDim.x + threadIdx.x;
    if (idx >= H_*32) return;
    int h = idx >> 5, j = idx & 31;
    float v = 0.f;
    if (j < 30){ int n = j/3, c = j - 3*n; v = sem_w[(n*H_+h)*C_ + c]; }
    g_W2[idx] = v;
}

// ---------------- K1: sem = x @ W2 + sem_b  (32768x768 @ 768x30) ----------------
// BM=128, BN=32(30 valid), BK=16, 256 threads, per-thread 8x2
__global__ void sem_gemm_kernel(const float* __restrict__ X, const float* __restrict__ semb){
    __shared__ float As[16][128];
    __shared__ float Bs[16][32];
    int tid = threadIdx.x;
    int m0 = blockIdx.x * 128;
    int tx = tid & 15, ty = tid >> 4;
    float acc[8][2] = {};
    for (int k0 = 0; k0 < H_; k0 += 16){
        #pragma unroll
        for (int i = 0; i < 2; i++){
            int p = tid*2 + i;
            int ar = p >> 2, ac = (p & 3) << 2;
            float4 v = *(const float4*)&X[(size_t)(m0+ar)*H_ + k0 + ac];
            As[ac+0][ar]=v.x; As[ac+1][ar]=v.y; As[ac+2][ar]=v.z; As[ac+3][ar]=v.w;
        }
        if (tid < 128){
            int br = tid >> 3, bc = (tid & 7) << 2;
            *(float4*)&Bs[br][bc] = *(const float4*)&g_W2[(k0+br)*32 + bc];
        }
        __syncthreads();
        #pragma unroll
        for (int k = 0; k < 16; k++){
            float a[8], b0 = Bs[k][tx*2], b1 = Bs[k][tx*2+1];
            #pragma unroll
            for (int i=0;i<8;i++) a[i] = As[k][ty*8+i];
            #pragma unroll
            for (int i=0;i<8;i++){ acc[i][0] += a[i]*b0; acc[i][1] += a[i]*b1; }
        }
        __syncthreads();
    }
    #pragma unroll
    for (int i=0;i<8;i++){
        int r = m0 + ty*8 + i;
        #pragma unroll
        for (int j=0;j<2;j++){
            int c = tx*2 + j;
            if (c < 30) g_sem[(size_t)r*30 + c] = acc[i][j] + semb[c];
        }
    }
}

// ---------------- K2: squash + dynamic routing (one thread per m) ----------------
__global__ void routing_kernel(const float* __restrict__ route_w){
    __shared__ float ssem[256*30];
    __shared__ float srw[K_*N_*C_*C_];  // 270
    int m0 = blockIdx.x * 256;
    for (int i = threadIdx.x; i < 256*30; i += 256) ssem[i] = g_sem[(size_t)m0*30 + i];
    if (threadIdx.x < 270) srw[threadIdx.x] = route_w[threadIdx.x];
    __syncthreads();
    int t = g_t;
    int m = m0 + threadIdx.x;

    float v[30];
    #pragma unroll
    for (int i=0;i<30;i++) v[i] = ssem[threadIdx.x*30+i];   // layout n*3+c

    // squash over n for each c; build u_flat[q], q = c*10+n; u[n'][c'] = u_flat[n'*3+c']
    float u[30];
    #pragma unroll
    for (int c=0;c<3;c++){
        float sn = 1e-16f;
        #pragma unroll
        for (int n=0;n<10;n++){ float xx = v[n*3+c]; sn += xx*xx; }
        float scale = (sn/(1.f+sn)) * rsqrtf(sn);
        #pragma unroll
        for (int n=0;n<10;n++) u[c*10+n] = v[n*3+c]*scale;
    }

    for (int k=0;k<3;k++){
        float pri[10][3];
        #pragma unroll
        for (int np=0;np<10;np++){
            #pragma unroll
            for (int d=0;d<3;d++){
                float s = 0.f;
                #pragma unroll
                for (int cp=0;cp<3;cp++)
                    s += u[np*3+cp] * srw[((k*10+np)*3+cp)*3+d];
                pri[np][d]=s;
            }
        }
        float logit[10];
        #pragma unroll
        for (int n=0;n<10;n++) logit[n]=0.f;
        float vt0=0.f, vt1=0.f, vt2=0.f;
        #pragma unroll
        for (int it=0; it<3; it++){
            float mx = -1e30f;
            #pragma unroll
            for (int n=0;n<10;n++){ logit[n] = (n<=t)?logit[n]:-10000.f; mx = fmaxf(mx, logit[n]); }
            float p[10]; float sum=0.f;
            #pragma unroll
            for (int n=0;n<10;n++){ p[n]=expf(logit[n]-mx); sum+=p[n]; }
            float inv = 1.f/sum;
            vt0=vt1=vt2=0.f;
            #pragma unroll
            for (int n=0;n<10;n++){
                float w = p[n]*inv;
                vt0 += w*pri[n][0]; vt1 += w*pri[n][1]; vt2 += w*pri[n][2];
            }
            if (it<2){
                float sn = vt0*vt0+vt1*vt1+vt2*vt2+1e-16f;
                float scale = (sn/(1.f+sn))*rsqrtf(sn);
                #pragma unroll
                for (int n=0;n<10;n++)
                    logit[n] += scale*(pri[n][0]*vt0+pri[n][1]*vt1+pri[n][2]*vt2);
            }
        }
        size_t base = ((size_t)k*M_ + m)*3;
        g_vote[base+0]=vt0; g_vote[base+1]=vt1; g_vote[base+2]=vt2;
    }
}

// ---------------- K3: h2 = x + (vote9 @ larger_w + larger_b) * glarger ----------------
// 16 rows per block, 256 threads, each thread owns 3 fixed columns (weights in regs)
__global__ void h2_kernel(const float* __restrict__ X,
                          const float* __restrict__ lw, const float* __restrict__ lb){
    __shared__ float sv[16*9];
    int r0 = blockIdx.x * 16;
    if (threadIdx.x < 144) sv[threadIdx.x] = g_vote[(size_t)r0*9 + threadIdx.x];
    float w[3][9], bb[3], gl[3];
    #pragma unroll
    for (int j=0;j<3;j++){
        int h = threadIdx.x + j*256;
        #pragma unroll
        for (int e=0;e<9;e++) w[j][e] = lw[e*H_ + h];
        bb[j] = lb[h]; gl[j] = g_gl[h];
    }
    __syncthreads();
    for (int r=0;r<16;r++){
        int m = r0 + r;
        float vv[9];
        #pragma unroll
        for (int e=0;e<9;e++) vv[e]=sv[r*9+e];
        #pragma unroll
        for (int j=0;j<3;j++){
            int h = threadIdx.x + j*256;
            float cap = bb[j];
            #pragma unroll
            for (int e=0;e<9;e++) cap += vv[e]*w[j][e];
            g_h2[(size_t)m*H_+h] = X[(size_t)m*H_+h] + cap*gl[j];
        }
    }
}

// ---------------- K4/K5: 128x128x8 SGEMM with fused gelu/gate epilogues ----------------
// EPI=1: g_a1 = gelu(g_h2 @ B + bias) * g_gate1
// EPI=2: out  = resid + gelu(g_a1 @ B + bias) * g_gate2
template<int EPI>
__global__ void sgemm_epi(const float* __restrict__ Bm, float* __restrict__ OutP,
                          int N, int K,
                          const float* __restrict__ bias,
                          const float* __restrict__ resid){
    __shared__ float As[8][128];
    __shared__ float Bs[8][128];
    const float* A    = (EPI==1) ? g_h2 : g_a1;
    float*       Cm   = (EPI==1) ? g_a1 : OutP;
    const float* gate = (EPI==1) ? g_gate1 : g_gate2;

    int tid = threadIdx.x;
    int tx = tid & 15, ty = tid >> 4;
    int bm = blockIdx.y, bn = blockIdx.x;
    const float* Ab = A + (size_t)bm*128*K;
    const float* Bb = Bm + (size_t)bn*128;
    float acc[8][8] = {};
    int arow = tid >> 1, acol = (tid & 1) << 2;
    int brow = tid >> 5, bcol = (tid & 31) << 2;

    for (int k0 = 0; k0 < K; k0 += 8){
        float4 av = *(const float4*)&Ab[(size_t)arow*K + k0 + acol];
        float4 bv = *(const float4*)&Bb[(size_t)(k0+brow)*N + bcol];
        As[acol+0][arow]=av.x; As[acol+1][arow]=av.y; As[acol+2][arow]=av.z; As[acol+3][arow]=av.w;
        *(float4*)&Bs[brow][bcol] = bv;
        __syncthreads();
        #pragma unroll
        for (int k=0;k<8;k++){
            float a[8], b[8];
            #pragma unroll
            for (int i=0;i<8;i++) a[i]=As[k][ty*8+i];
            #pragma unroll
            for (int j=0;j<8;j++) b[j]=Bs[k][tx*8+j];
            #pragma unroll
            for (int i=0;i<8;i++)
                #pragma unroll
                for (int j=0;j<8;j++)
                    acc[i][j] += a[i]*b[j];
        }
        __syncthreads();
    }
    #pragma unroll
    for (int i=0;i<8;i++){
        int r = bm*128 + ty*8 + i;
        #pragma unroll
        for (int j=0;j<8;j++){
            int c = bn*128 + tx*8 + j;
            float v = acc[i][j] + bias[c];
            v = gelu_exact(v) * gate[c];
            if (EPI==2) v += resid[(size_t)r*N + c];
            Cm[(size_t)r*N + c] = v;
        }
    }
}

// ---------------- launch ----------------
extern "C" void kernel_launch(void* const* d_in, const int* in_sizes, int n_in,
                              void* d_out, int out_size){
    const float* x       = (const float*)d_in[0];
    const void*  tptr    = d_in[1];
    const void*  sptr    = d_in[2];
    const float* fc1_w   = (const float*)d_in[3];
    const float* fc1_b   = (const float*)d_in[4];
    const float* fc2_w   = (const float*)d_in[5];
    const float* fc2_b   = (const float*)d_in[6];
    const float* efc1    = (const float*)d_in[7];
    const float* efc2    = (const float*)d_in[8];
    const float* sem_w   = (const float*)d_in[9];
    const float* sem_b   = (const float*)d_in[10];
    const float* route_w = (const float*)d_in[11];
    const float* larger_w= (const float*)d_in[12];
    const float* larger_b= (const float*)d_in[13];
    const float* elarger = (const float*)d_in[14];
    float* out = (float*)d_out;
    (void)in_sizes; (void)n_in; (void)out_size;

    prep_kernel<<<1, 768>>>(tptr, sptr, efc1, efc2, elarger);
    w2_kernel<<<(H_*32 + 255)/256, 256>>>(sem_w);
    sem_gemm_kernel<<<M_/128, 256>>>(x, sem_b);
    routing_kernel<<<M_/256, 256>>>(route_w);
    h2_kernel<<<M_/16, 256>>>(x, larger_w, larger_b);
    sgemm_epi<1><<<dim3(A_/128, M_/128), 256>>>(fc1_w, nullptr, A_, H_, fc1_b, nullptr);
    sgemm_epi<2><<<dim3(H_/128, M_/128), 256>>>(fc2_w, out,     H_, A_, fc2_b, x);
}

// round 3
// speedup vs baseline: 2.7098x; 2.7098x over previous
#include <cuda_runtime.h>
#include <math.h>
#include <cstdint>

#define B_ 256
#define S_ 128
#define H_ 768
#define A_ 512
#define N_ 10
#define C_ 3
#define K_ 3
#define M_ (B_*S_)   // 32768

// ---------------- scratch (static device globals; no allocation) ----------------
__device__ float g_W2[H_*32];                 // sem weights rearranged: [h][j], j=n*3+c (30 valid, 2 zero)
__device__ float g_sem[(size_t)M_*30];        // semantic linear out, layout j = n*3+c
__device__ float g_vote[(size_t)K_*M_*C_];    // vote (K,M,C) contiguous == h view
__device__ float g_h2[(size_t)M_*H_];         // x + gated capsule output
__device__ float g_a1[(size_t)M_*A_];         // adapter hidden
__device__ float g_gate1[A_];
__device__ float g_gate2[H_];
__device__ float g_gl[H_];
__device__ int   g_t;

// ---------------- helpers ----------------
__device__ __forceinline__ uint32_t smem_u32(const void* p){
    uint32_t a;
    asm("{ .reg .u64 t; cvta.to.shared.u64 t, %1; cvt.u32.u64 %0, t; }" : "=r"(a) : "l"(p));
    return a;
}
__device__ __forceinline__ void cp_async16(uint32_t smem_addr, const void* gptr){
    asm volatile("cp.async.cg.shared.global [%0], [%1], 16;" :: "r"(smem_addr), "l"(gptr));
}
__device__ __forceinline__ uint32_t f2tf32(float x){
    uint32_t r; asm("cvt.rna.tf32.f32 %0, %1;" : "=r"(r) : "f"(x)); return r;
}
__device__ __forceinline__ void mma_tf32(float* c, const uint32_t* a, const uint32_t* b){
    asm volatile("mma.sync.aligned.m16n8k8.row.col.f32.tf32.tf32.f32 "
        "{%0,%1,%2,%3}, {%4,%5,%6,%7}, {%8,%9}, {%0,%1,%2,%3};"
        : "+f"(c[0]), "+f"(c[1]), "+f"(c[2]), "+f"(c[3])
        : "r"(a[0]), "r"(a[1]), "r"(a[2]), "r"(a[3]), "r"(b[0]), "r"(b[1]));
}

__device__ __forceinline__ int decode_int(const void* p){
    int v = *(const int*)p;
    if (v >= -1000000 && v <= 1000000) return v;
    return (int)__int_as_float(v);
}
__device__ __forceinline__ float decode_float(const void* p){
    int v = *(const int*)p;
    if (v >= -1000000 && v <= 1000000) return (float)v;
    return __int_as_float(v);
}
__device__ __forceinline__ float sigmoidf_(float x){ return 1.f/(1.f+expf(-x)); }
__device__ __forceinline__ float gelu_exact(float x){
    return 0.5f*x*(1.f+erff(x*0.70710678118654752f));
}

// ---------------- K0: decode scalars, precompute HAT gates ----------------
__global__ void prep_kernel(const void* tptr, const void* sptr,
                            const float* __restrict__ efc1,
                            const float* __restrict__ efc2,
                            const float* __restrict__ elarger){
    __shared__ int st; __shared__ float ssf;
    if (threadIdx.x == 0){
        int t = decode_int(tptr);
        float sf = decode_float(sptr);
        st = t; ssf = sf; g_t = t;
    }
    __syncthreads();
    int t = st; float sf = ssf;
    int i = threadIdx.x;
    if (i < A_) g_gate1[i] = sigmoidf_(sf*efc1[t*A_+i]);
    if (i < H_){
        g_gate2[i] = sigmoidf_(sf*efc2[t*H_+i]);
        g_gl[i]    = sigmoidf_(sf*elarger[t*H_+i]);
    }
}

// ---------------- K0b: rearrange sem_w (N,H,C) -> W2[h][j], j=n*3+c, padded to 32 ----------------
__global__ void w2_kernel(const float* __restrict__ sem_w){
    int idx = blockIdx.x*blockDim.x + threadIdx.x;
    if (idx >= H_*32) return;
    int h = idx >> 5, j = idx & 31;
    float v = 0.f;
    if (j < 30){ int n = j/3, c = j - 3*n; v = sem_w[(n*H_+h)*C_ + c]; }
    g_W2[idx] = v;
}

// ---------------- tf32 mma.sync GEMM with fused epilogues ----------------
// C[M x NOUT] over tiles BM=128 x BN. A: [M,KTOT] row-major. B: [KTOT, LDB] row-major (k rows).
// EPI 0: g_sem = x @ g_W2 + sem_b           (BN=32, NOUT=30)
// EPI 1: g_a1  = gelu(g_h2 @ fc1_w + b)*g1  (BN=128, NOUT=512)
// EPI 2: out   = x + gelu(g_a1 @ fc2_w + b)*g2 (BN=128, NOUT=768)
template<int KTOT, int NOUT, int BN, int LDB, int EPI>
__global__ void __launch_bounds__(256) mma_gemm(
    const float* __restrict__ Ain, const float* __restrict__ Bglob,
    float* __restrict__ Cout,
    const float* __restrict__ bias, const float* __restrict__ resid)
{
    constexpr int BM = 128, BK = 16;
    constexpr int SA = BK + 4;        // 20 floats: conflict-free A frag loads
    constexpr int SB = BN + 8;        // conflict-free B frag loads
    constexpr int NKC = KTOT / BK;
    constexpr int WN  = BN / 2;       // warp n-extent (4x2 warp grid)
    constexpr int NTW = WN / 8;       // n-tiles per warp
    constexpr int AB = BM*SA;         // floats per A buffer
    constexpr int BB = BK*SB;         // floats per B buffer

    __shared__ float sm[2*AB + 2*BB];
    const uint32_t sbase = smem_u32(sm);
    const uint32_t bbase = sbase + 2*AB*4;

    const int tid = threadIdx.x, lane = tid & 31, wid = tid >> 5;
    const int warp_m = wid & 3, warp_n = wid >> 2;
    const int m0 = blockIdx.y * BM, n0 = blockIdx.x * BN;

    const float* Ap = (EPI==0) ? Ain : (EPI==1) ? (const float*)g_h2 : (const float*)g_a1;
    const float* Bp = (EPI==0) ? (const float*)g_W2 : Bglob;

    float acc[2][NTW][4];
    #pragma unroll
    for (int mt=0;mt<2;mt++)
        #pragma unroll
        for (int nt=0;nt<NTW;nt++)
            #pragma unroll
            for (int e=0;e<4;e++) acc[mt][nt][e]=0.f;

    auto loadA = [&](int kc, int buf){
        const float* src = Ap + (size_t)m0*KTOT + kc*BK;
        #pragma unroll
        for (int i=0;i<2;i++){
            int q = tid + 256*i;            // 512 chunks of 16B
            int r = q >> 2, s = q & 3;
            cp_async16(sbase + (buf*AB + r*SA + s*4)*4, src + (size_t)r*KTOT + s*4);
        }
    };
    auto loadB = [&](int kc, int buf){
        const float* src = Bp + (size_t)(kc*BK)*LDB + n0;
        if (BN == 128){
            #pragma unroll
            for (int i=0;i<2;i++){
                int q = tid + 256*i;        // 512 chunks
                int r = q >> 5, s = q & 31;
                cp_async16(bbase + (buf*BB + r*SB + s*4)*4, src + (size_t)r*LDB + s*4);
            }
        } else {
            if (tid < 128){
                int r = tid >> 3, s = tid & 7;   // 16 rows x 8 chunks
                cp_async16(bbase + (buf*BB + r*SB + s*4)*4, src + (size_t)r*LDB + s*4);
            }
        }
    };
    auto compute = [&](int buf){
        const float* As = sm + buf*AB;
        const float* Bs = sm + 2*AB + buf*BB;
        #pragma unroll
        for (int ks=0; ks<2; ks++){
            uint32_t af[2][4];
            const int ar = warp_m*32 + (lane>>2);
            const int ac = ks*8 + (lane&3);
            #pragma unroll
            for (int mt=0;mt<2;mt++){
                af[mt][0] = f2tf32(As[(ar+mt*16  )*SA + ac  ]);
                af[mt][1] = f2tf32(As[(ar+mt*16+8)*SA + ac  ]);
                af[mt][2] = f2tf32(As[(ar+mt*16  )*SA + ac+4]);
                af[mt][3] = f2tf32(As[(ar+mt*16+8)*SA + ac+4]);
            }
            uint32_t bf[NTW][2];
            const int br = ks*8 + (lane&3);
            const int bc = warp_n*WN + (lane>>2);
            #pragma unroll
            for (int nt=0;nt<NTW;nt++){
                bf[nt][0] = f2tf32(Bs[(br  )*SB + bc + nt*8]);
                bf[nt][1] = f2tf32(Bs[(br+4)*SB + bc + nt*8]);
            }
            #pragma unroll
            for (int mt=0;mt<2;mt++)
                #pragma unroll
                for (int nt=0;nt<NTW;nt++)
                    mma_tf32(acc[mt][nt], af[mt], bf[nt]);
        }
    };

    loadA(0,0); loadB(0,0);
    asm volatile("cp.async.commit_group;" ::: "memory");

    for (int kc = 0; kc < NKC; kc++){
        if (kc+1 < NKC){
            loadA(kc+1, (kc+1)&1);
            loadB(kc+1, (kc+1)&1);
            asm volatile("cp.async.commit_group;" ::: "memory");
            asm volatile("cp.async.wait_group 1;" ::: "memory");
        } else {
            asm volatile("cp.async.wait_group 0;" ::: "memory");
        }
        __syncthreads();
        compute(kc&1);
        __syncthreads();
    }

    // ---------------- epilogue ----------------
    const float* gate = (EPI==1) ? (const float*)g_gate1 : (const float*)g_gate2;
    #pragma unroll
    for (int mt=0;mt<2;mt++){
        #pragma unroll
        for (int nt=0;nt<NTW;nt++){
            int row = m0 + warp_m*32 + mt*16 + (lane>>2);
            int col = n0 + warp_n*WN + nt*8 + (lane&3)*2;
            #pragma unroll
            for (int half=0; half<2; half++){
                int r = row + half*8;
                float v0 = acc[mt][nt][half*2+0];
                float v1 = acc[mt][nt][half*2+1];
                if (EPI == 0){
                    if (col   < 30) Cout[(size_t)r*30 + col  ] = v0 + bias[col];
                    if (col+1 < 30) Cout[(size_t)r*30 + col+1] = v1 + bias[col+1];
                } else {
                    v0 = gelu_exact(v0 + bias[col  ]) * gate[col  ];
                    v1 = gelu_exact(v1 + bias[col+1]) * gate[col+1];
                    size_t o = (size_t)r*NOUT + col;
                    if (EPI == 2){ v0 += resid[o]; v1 += resid[o+1]; }
                    float2 vv = make_float2(v0, v1);
                    *(float2*)((EPI==1 ? (float*)g_a1 : Cout) + o) = vv;
                }
            }
        }
    }
}

// ---------------- K2: squash + dynamic routing (one thread per m) ----------------
__global__ void routing_kernel(const float* __restrict__ route_w){
    __shared__ float ssem[256*30];
    __shared__ float srw[K_*N_*C_*C_];  // 270
    int m0 = blockIdx.x * 256;
    for (int i = threadIdx.x; i < 256*30; i += 256) ssem[i] = g_sem[(size_t)m0*30 + i];
    if (threadIdx.x < 270) srw[threadIdx.x] = route_w[threadIdx.x];
    __syncthreads();
    int t = g_t;
    int m = m0 + threadIdx.x;

    float v[30];
    #pragma unroll
    for (int i=0;i<30;i++) v[i] = ssem[threadIdx.x*30+i];

    float u[30];
    #pragma unroll
    for (int c=0;c<3;c++){
        float sn = 1e-16f;
        #pragma unroll
        for (int n=0;n<10;n++){ float xx = v[n*3+c]; sn += xx*xx; }
        float scale = (sn/(1.f+sn)) * rsqrtf(sn);
        #pragma unroll
        for (int n=0;n<10;n++) u[c*10+n] = v[n*3+c]*scale;
    }

    for (int k=0;k<3;k++){
        float pri[10][3];
        #pragma unroll
        for (int np=0;np<10;np++){
            #pragma unroll
            for (int d=0;d<3;d++){
                float s = 0.f;
                #pragma unroll
                for (int cp=0;cp<3;cp++)
                    s += u[np*3+cp] * srw[((k*10+np)*3+cp)*3+d];
                pri[np][d]=s;
            }
        }
        float logit[10];
        #pragma unroll
        for (int n=0;n<10;n++) logit[n]=0.f;
        float vt0=0.f, vt1=0.f, vt2=0.f;
        #pragma unroll
        for (int it=0; it<3; it++){
            float mx = -1e30f;
            #pragma unroll
            for (int n=0;n<10;n++){ logit[n] = (n<=t)?logit[n]:-10000.f; mx = fmaxf(mx, logit[n]); }
            float p[10]; float sum=0.f;
            #pragma unroll
            for (int n=0;n<10;n++){ p[n]=expf(logit[n]-mx); sum+=p[n]; }
            float inv = 1.f/sum;
            vt0=vt1=vt2=0.f;
            #pragma unroll
            for (int n=0;n<10;n++){
                float w = p[n]*inv;
                vt0 += w*pri[n][0]; vt1 += w*pri[n][1]; vt2 += w*pri[n][2];
            }
            if (it<2){
                float sn = vt0*vt0+vt1*vt1+vt2*vt2+1e-16f;
                float scale = (sn/(1.f+sn))*rsqrtf(sn);
                #pragma unroll
                for (int n=0;n<10;n++)
                    logit[n] += scale*(pri[n][0]*vt0+pri[n][1]*vt1+pri[n][2]*vt2);
            }
        }
        size_t base = ((size_t)k*M_ + m)*3;
        g_vote[base+0]=vt0; g_vote[base+1]=vt1; g_vote[base+2]=vt2;
    }
}

// ---------------- K3: h2 = x + (vote9 @ larger_w + larger_b) * glarger ----------------
__global__ void h2_kernel(const float* __restrict__ X,
                          const float* __restrict__ lw, const float* __restrict__ lb){
    __shared__ float sv[16*9];
    int r0 = blockIdx.x * 16;
    if (threadIdx.x < 144) sv[threadIdx.x] = g_vote[(size_t)r0*9 + threadIdx.x];
    float w[3][9], bb[3], gl[3];
    #pragma unroll
    for (int j=0;j<3;j++){
        int h = threadIdx.x + j*256;
        #pragma unroll
        for (int e=0;e<9;e++) w[j][e] = lw[e*H_ + h];
        bb[j] = lb[h]; gl[j] = g_gl[h];
    }
    __syncthreads();
    for (int r=0;r<16;r++){
        int m = r0 + r;
        float vv[9];
        #pragma unroll
        for (int e=0;e<9;e++) vv[e]=sv[r*9+e];
        #pragma unroll
        for (int j=0;j<3;j++){
            int h = threadIdx.x + j*256;
            float cap = bb[j];
            #pragma unroll
            for (int e=0;e<9;e++) cap += vv[e]*w[j][e];
            g_h2[(size_t)m*H_+h] = X[(size_t)m*H_+h] + cap*gl[j];
        }
    }
}

// ---------------- launch ----------------
extern "C" void kernel_launch(void* const* d_in, const int* in_sizes, int n_in,
                              void* d_out, int out_size){
    const float* x       = (const float*)d_in[0];
    const void*  tptr    = d_in[1];
    const void*  sptr    = d_in[2];
    const float* fc1_w   = (const float*)d_in[3];
    const float* fc1_b   = (const float*)d_in[4];
    const float* fc2_w   = (const float*)d_in[5];
    const float* fc2_b   = (const float*)d_in[6];
    const float* efc1    = (const float*)d_in[7];
    const float* efc2    = (const float*)d_in[8];
    const float* sem_w   = (const float*)d_in[9];
    const float* sem_b   = (const float*)d_in[10];
    const float* route_w = (const float*)d_in[11];
    const float* larger_w= (const float*)d_in[12];
    const float* larger_b= (const float*)d_in[13];
    const float* elarger = (const float*)d_in[14];
    float* out = (float*)d_out;
    (void)in_sizes; (void)n_in; (void)out_size;

    static float* sem_ptr = nullptr;
    if (!sem_ptr) cudaGetSymbolAddress((void**)&sem_ptr, g_sem);

    prep_kernel<<<1, 768>>>(tptr, sptr, efc1, efc2, elarger);
    w2_kernel<<<(H_*32 + 255)/256, 256>>>(sem_w);

    // sem GEMM (tf32 mma): (32768 x 768) @ (768 x 30)
    mma_gemm<768, 30, 32, 32, 0><<<dim3(1, M_/128), 256>>>(x, nullptr, sem_ptr, sem_b, nullptr);
    routing_kernel<<<M_/256, 256>>>(route_w);
    h2_kernel<<<M_/16, 256>>>(x, larger_w, larger_b);
    // adapter GEMM1: (32768 x 768) @ (768 x 512), gelu*gate1 -> g_a1
    mma_gemm<768, 512, 128, 512, 1><<<dim3(A_/128, M_/128), 256>>>(nullptr, fc1_w, nullptr, fc1_b, nullptr);
    // adapter GEMM2: (32768 x 512) @ (512 x 768), gelu*gate2 + x -> out
    mma_gemm<512, 768, 128, 768, 2><<<dim3(H_/128, M_/128), 256>>>(nullptr, fc2_w, out, fc2_b, x);
}

// round 5
// speedup vs baseline: 2.8349x; 1.0461x over previous
#include <cuda_runtime.h>
#include <math.h>
#include <cstdint>

#define B_ 256
#define S_ 128
#define H_ 768
#define A_ 512
#define N_ 10
#define C_ 3
#define K_ 3
#define M_ (B_*S_)   // 32768

// ---------------- scratch (static device globals; no allocation) ----------------
__device__ float g_W2[H_*32];                 // sem weights rearranged: [h][j], j=n*3+c (30 valid, 2 zero)
__device__ float g_sem[(size_t)M_*30];        // semantic linear out, layout j = n*3+c
__device__ float g_vote[(size_t)K_*M_*C_];    // vote (K,M,C) contiguous; h view = flat reinterpretation
__device__ float g_h2[(size_t)M_*H_];         // x + gated capsule output
__device__ float g_a1[(size_t)M_*A_];         // adapter hidden
__device__ float g_gate1[A_];
__device__ float g_gate2[H_];
__device__ float g_gl[H_];
__device__ int   g_t;

// ---------------- helpers ----------------
__device__ __forceinline__ uint32_t smem_u32(const void* p){
    uint32_t a;
    asm("{ .reg .u64 t; cvta.to.shared.u64 t, %1; cvt.u32.u64 %0, t; }" : "=r"(a) : "l"(p));
    return a;
}
__device__ __forceinline__ void cp_async16(uint32_t smem_addr, const void* gptr){
    asm volatile("cp.async.cg.shared.global [%0], [%1], 16;" :: "r"(smem_addr), "l"(gptr));
}
__device__ __forceinline__ void mma_tf32(float* c, const uint32_t* a, const uint32_t* b){
    asm volatile("mma.sync.aligned.m16n8k8.row.col.f32.tf32.tf32.f32 "
        "{%0,%1,%2,%3}, {%4,%5,%6,%7}, {%8,%9}, {%0,%1,%2,%3};"
        : "+f"(c[0]), "+f"(c[1]), "+f"(c[2]), "+f"(c[3])
        : "r"(a[0]), "r"(a[1]), "r"(a[2]), "r"(a[3]), "r"(b[0]), "r"(b[1]));
}

__device__ __forceinline__ int decode_int(const void* p){
    int v = *(const int*)p;
    if (v >= -1000000 && v <= 1000000) return v;
    return (int)__int_as_float(v);
}
__device__ __forceinline__ float decode_float(const void* p){
    int v = *(const int*)p;
    if (v >= -1000000 && v <= 1000000) return (float)v;
    return __int_as_float(v);
}
__device__ __forceinline__ float sigmoidf_(float x){ return 1.f/(1.f+expf(-x)); }
__device__ __forceinline__ float gelu_exact(float x){
    return 0.5f*x*(1.f+erff(x*0.70710678118654752f));
}

// ---------------- K0: decode scalars, precompute HAT gates ----------------
__global__ void prep_kernel(const void* tptr, const void* sptr,
                            const float* __restrict__ efc1,
                            const float* __restrict__ efc2,
                            const float* __restrict__ elarger){
    __shared__ int st; __shared__ float ssf;
    if (threadIdx.x == 0){
        int t = decode_int(tptr);
        float sf = decode_float(sptr);
        st = t; ssf = sf; g_t = t;
    }
    __syncthreads();
    int t = st; float sf = ssf;
    int i = threadIdx.x;
    if (i < A_) g_gate1[i] = sigmoidf_(sf*efc1[t*A_+i]);
    if (i < H_){
        g_gate2[i] = sigmoidf_(sf*efc2[t*H_+i]);
        g_gl[i]    = sigmoidf_(sf*elarger[t*H_+i]);
    }
}

// ---------------- K0b: rearrange sem_w (N,H,C) -> W2[h][j], j=n*3+c, padded to 32 ----------------
__global__ void w2_kernel(const float* __restrict__ sem_w){
    int idx = blockIdx.x*blockDim.x + threadIdx.x;
    if (idx >= H_*32) return;
    int h = idx >> 5, j = idx & 31;
    float v = 0.f;
    if (j < 30){ int n = j/3, c = j - 3*n; v = sem_w[(n*H_+h)*C_ + c]; }
    g_W2[idx] = v;
}

// ---------------- tf32 mma.sync GEMM, 3-stage cp.async ring, fused epilogues ----------------
// EPI 0: g_sem = x @ g_W2 + sem_b              (BN=32, NOUT=30)
// EPI 1: g_a1  = gelu(g_h2 @ fc1_w + b)*g1     (BN=128, NOUT=512)
// EPI 2: out   = x + gelu(g_a1 @ fc2_w + b)*g2 (BN=128, NOUT=768)
template<int KTOT, int NOUT, int BN, int LDB, int EPI>
__global__ void __launch_bounds__(256) mma_gemm(
    const float* __restrict__ Ain, const float* __restrict__ Bglob,
    float* __restrict__ Cout,
    const float* __restrict__ bias, const float* __restrict__ resid)
{
    constexpr int BM = 128, BK = 16;
    constexpr int SA = BK + 4;        // 20 floats: conflict-free A frag loads
    constexpr int SB = BN + 8;        // conflict-free B frag loads
    constexpr int NKC = KTOT / BK;
    constexpr int WN  = BN / 2;       // warp n-extent (4x2 warp grid)
    constexpr int NTW = WN / 8;       // n-tiles per warp
    constexpr int AB = BM*SA;         // floats per A stage
    constexpr int BB = BK*SB;         // floats per B stage

    extern __shared__ float sm[];
    float* Asm = sm;
    float* Bsm = sm + 3*AB;
    const uint32_t sbase = smem_u32(sm);
    const uint32_t bbase = sbase + 3*AB*4;

    const int tid = threadIdx.x, lane = tid & 31, wid = tid >> 5;
    const int warp_m = wid & 3, warp_n = wid >> 2;
    const int m0 = blockIdx.y * BM, n0 = blockIdx.x * BN;

    const float* Ap = (EPI==0) ? Ain : (EPI==1) ? (const float*)g_h2 : (const float*)g_a1;
    const float* Bp = (EPI==0) ? (const float*)g_W2 : Bglob;

    float acc[2][NTW][4];
    #pragma unroll
    for (int mt=0;mt<2;mt++)
        #pragma unroll
        for (int nt=0;nt<NTW;nt++)
            #pragma unroll
            for (int e=0;e<4;e++) acc[mt][nt][e]=0.f;

    auto loadAB = [&](int kc){
        const int st = kc % 3;
        const float* srcA = Ap + (size_t)m0*KTOT + kc*BK;
        #pragma unroll
        for (int i=0;i<2;i++){
            int q = tid + 256*i;            // 512 chunks of 16B
            int r = q >> 2, s = q & 3;
            cp_async16(sbase + (st*AB + r*SA + s*4)*4, srcA + (size_t)r*KTOT + s*4);
        }
        const float* srcB = Bp + (size_t)(kc*BK)*LDB + n0;
        if (BN == 128){
            #pragma unroll
            for (int i=0;i<2;i++){
                int q = tid + 256*i;        // 512 chunks
                int r = q >> 5, s = q & 31;
                cp_async16(bbase + (st*BB + r*SB + s*4)*4, srcB + (size_t)r*LDB + s*4);
            }
        } else {
            if (tid < 128){
                int r = tid >> 3, s = tid & 7;   // 16 rows x 8 chunks
                cp_async16(bbase + (st*BB + r*SB + s*4)*4, srcB + (size_t)r*LDB + s*4);
            }
        }
        asm volatile("cp.async.commit_group;" ::: "memory");
    };

    auto compute = [&](int st){
        const float* As = Asm + st*AB;
        const float* Bs = Bsm + st*BB;
        #pragma unroll
        for (int ks=0; ks<2; ks++){
            uint32_t af[2][4];
            const int ar = warp_m*32 + (lane>>2);
            const int ac = ks*8 + (lane&3);
            #pragma unroll
            for (int mt=0;mt<2;mt++){
                af[mt][0] = __float_as_uint(As[(ar+mt*16  )*SA + ac  ]);
                af[mt][1] = __float_as_uint(As[(ar+mt*16+8)*SA + ac  ]);
                af[mt][2] = __float_as_uint(As[(ar+mt*16  )*SA + ac+4]);
                af[mt][3] = __float_as_uint(As[(ar+mt*16+8)*SA + ac+4]);
            }
            uint32_t bf[NTW][2];
            const int br = ks*8 + (lane&3);
            const int bc = warp_n*WN + (lane>>2);
            #pragma unroll
            for (int nt=0;nt<NTW;nt++){
                bf[nt][0] = __float_as_uint(Bs[(br  )*SB + bc + nt*8]);
                bf[nt][1] = __float_as_uint(Bs[(br+4)*SB + bc + nt*8]);
            }
            #pragma unroll
            for (int mt=0;mt<2;mt++)
                #pragma unroll
                for (int nt=0;nt<NTW;nt++)
                    mma_tf32(acc[mt][nt], af[mt], bf[nt]);
        }
    };

    // prologue: stage 0 and 1
    loadAB(0);
    if (NKC > 1) loadAB(1);

    for (int kc = 0; kc < NKC; kc++){
        if (kc + 1 < NKC) asm volatile("cp.async.wait_group 1;" ::: "memory");
        else              asm volatile("cp.async.wait_group 0;" ::: "memory");
        __syncthreads();
        if (kc + 2 < NKC) loadAB(kc + 2);
        compute(kc % 3);
    }

    // ---------------- epilogue ----------------
    const float* gate = (EPI==1) ? (const float*)g_gate1 : (const float*)g_gate2;
    #pragma unroll
    for (int mt=0;mt<2;mt++){
        #pragma unroll
        for (int nt=0;nt<NTW;nt++){
            int row = m0 + warp_m*32 + mt*16 + (lane>>2);
            int col = n0 + warp_n*WN + nt*8 + (lane&3)*2;
            #pragma unroll
            for (int half=0; half<2; half++){
                int r = row + half*8;
                float v0 = acc[mt][nt][half*2+0];
                float v1 = acc[mt][nt][half*2+1];
                if (EPI == 0){
                    if (col   < 30) Cout[(size_t)r*30 + col  ] = v0 + bias[col];
                    if (col+1 < 30) Cout[(size_t)r*30 + col+1] = v1 + bias[col+1];
                } else {
                    v0 = gelu_exact(v0 + bias[col  ]) * gate[col  ];
                    v1 = gelu_exact(v1 + bias[col+1]) * gate[col+1];
                    size_t o = (size_t)r*NOUT + col;
                    if (EPI == 2){ v0 += resid[o]; v1 += resid[o+1]; }
                    float2 vv = make_float2(v0, v1);
                    *(float2*)((EPI==1 ? (float*)g_a1 : Cout) + o) = vv;
                }
            }
        }
    }
}

// ---------------- K2: squash + dynamic routing (one thread per m) ----------------
__global__ void routing_kernel(const float* __restrict__ route_w){
    __shared__ float ssem[256*30];
    __shared__ float srw[K_*N_*C_*C_];  // 270
    int m0 = blockIdx.x * 256;
    for (int i = threadIdx.x; i < 256*30; i += 256) ssem[i] = g_sem[(size_t)m0*30 + i];
    if (threadIdx.x < 270) srw[threadIdx.x] = route_w[threadIdx.x];
    __syncthreads();
    int t = g_t;
    int m = m0 + threadIdx.x;

    float v[30];
    #pragma unroll
    for (int i=0;i<30;i++) v[i] = ssem[threadIdx.x*30+i];

    float u[30];
    #pragma unroll
    for (int c=0;c<3;c++){
        float sn = 1e-16f;
        #pragma unroll
        for (int n=0;n<10;n++){ float xx = v[n*3+c]; sn += xx*xx; }
        float scale = (sn/(1.f+sn)) * rsqrtf(sn);
        #pragma unroll
        for (int n=0;n<10;n++) u[c*10+n] = v[n*3+c]*scale;
    }

    for (int k=0;k<3;k++){
        float pri[10][3];
        #pragma unroll
        for (int np=0;np<10;np++){
            #pragma unroll
            for (int d=0;d<3;d++){
                float s = 0.f;
                #pragma unroll
                for (int cp=0;cp<3;cp++)
                    s += u[np*3+cp] * srw[((k*10+np)*3+cp)*3+d];
                pri[np][d]=s;
            }
        }
        float logit[10];
        #pragma unroll
        for (int n=0;n<10;n++) logit[n]=0.f;
        float vt0=0.f, vt1=0.f, vt2=0.f;
        #pragma unroll
        for (int it=0; it<3; it++){
            float mx = -1e30f;
            #pragma unroll
            for (int n=0;n<10;n++){ logit[n] = (n<=t)?logit[n]:-10000.f; mx = fmaxf(mx, logit[n]); }
            float p[10]; float sum=0.f;
            #pragma unroll
            for (int n=0;n<10;n++){ p[n]=expf(logit[n]-mx); sum+=p[n]; }
            float inv = 1.f/sum;
            vt0=vt1=vt2=0.f;
            #pragma unroll
            for (int n=0;n<10;n++){
                float w = p[n]*inv;
                vt0 += w*pri[n][0]; vt1 += w*pri[n][1]; vt2 += w*pri[n][2];
            }
            if (it<2){
                float sn = vt0*vt0+vt1*vt1+vt2*vt2+1e-16f;
                float scale = (sn/(1.f+sn))*rsqrtf(sn);
                #pragma unroll
                for (int n=0;n<10;n++)
                    logit[n] += scale*(pri[n][0]*vt0+pri[n][1]*vt1+pri[n][2]*vt2);
            }
        }
        size_t base = ((size_t)k*M_ + m)*3;
        g_vote[base+0]=vt0; g_vote[base+1]=vt1; g_vote[base+2]=vt2;
    }
}

// ---------------- K3: h2 = x + (vote9 @ larger_w + larger_b) * glarger ----------------
__global__ void h2_kernel(const float* __restrict__ X,
                          const float* __restrict__ lw, const float* __restrict__ lb){
    __shared__ float sv[16*9];
    int r0 = blockIdx.x * 16;
    if (threadIdx.x < 144) sv[threadIdx.x] = g_vote[(size_t)r0*9 + threadIdx.x];
    float w[3][9], bb[3], gl[3];
    #pragma unroll
    for (int j=0;j<3;j++){
        int h = threadIdx.x + j*256;
        #pragma unroll
        for (int e=0;e<9;e++) w[j][e] = lw[e*H_ + h];
        bb[j] = lb[h]; gl[j] = g_gl[h];
    }
    __syncthreads();
    for (int r=0;r<16;r++){
        int m = r0 + r;
        float vv[9];
        #pragma unroll
        for (int e=0;e<9;e++) vv[e]=sv[r*9+e];
        #pragma unroll
        for (int j=0;j<3;j++){
            int h = threadIdx.x + j*256;
            float cap = bb[j];
            #pragma unroll
            for (int e=0;e<9;e++) cap += vv[e]*w[j][e];
            g_h2[(size_t)m*H_+h] = X[(size_t)m*H_+h] + cap*gl[j];
        }
    }
}

// ---------------- launch ----------------
extern "C" void kernel_launch(void* const* d_in, const int* in_sizes, int n_in,
                              void* d_out, int out_size){
    const float* x       = (const float*)d_in[0];
    const void*  tptr    = d_in[1];
    const void*  sptr    = d_in[2];
    const float* fc1_w   = (const float*)d_in[3];
    const float* fc1_b   = (const float*)d_in[4];
    const float* fc2_w   = (const float*)d_in[5];
    const float* fc2_b   = (const float*)d_in[6];
    const float* efc1    = (const float*)d_in[7];
    const float* efc2    = (const float*)d_in[8];
    const float* sem_w   = (const float*)d_in[9];
    const float* sem_b   = (const float*)d_in[10];
    const float* route_w = (const float*)d_in[11];
    const float* larger_w= (const float*)d_in[12];
    const float* larger_b= (const float*)d_in[13];
    const float* elarger = (const float*)d_in[14];
    float* out = (float*)d_out;
    (void)in_sizes; (void)n_in; (void)out_size;

    // dynamic smem sizes: 3 stages of (A:128*20 + B:BK*(BN+8)) floats
    const int SMEM_BIG = 3 * (128*20 + 16*136) * 4;   // 56832 B
    const int SMEM_SEM = 3 * (128*20 + 16*40)  * 4;   // 38400 B

    static float* sem_ptr = nullptr;
    if (!sem_ptr){
        cudaGetSymbolAddress((void**)&sem_ptr, g_sem);
        cudaFuncSetAttribute((const void*)mma_gemm<768, 512, 128, 512, 1>,
                             cudaFuncAttributeMaxDynamicSharedMemorySize, SMEM_BIG);
        cudaFuncSetAttribute((const void*)mma_gemm<512, 768, 128, 768, 2>,
                             cudaFuncAttributeMaxDynamicSharedMemorySize, SMEM_BIG);
    }

    prep_kernel<<<1, 768>>>(tptr, sptr, efc1, efc2, elarger);
    w2_kernel<<<(H_*32 + 255)/256, 256>>>(sem_w);

    // sem GEMM (tf32 mma): (32768 x 768) @ (768 x 30)
    mma_gemm<768, 30, 32, 32, 0><<<dim3(1, M_/128), 256, SMEM_SEM>>>(x, nullptr, sem_ptr, sem_b, nullptr);
    routing_kernel<<<M_/256, 256>>>(route_w);
    h2_kernel<<<M_/16, 256>>>(x, larger_w, larger_b);
    // adapter GEMM1: (32768 x 768) @ (768 x 512), gelu*gate1 -> g_a1
    mma_gemm<768, 512, 128, 512, 1><<<dim3(A_/128, M_/128), 256, SMEM_BIG>>>(nullptr, fc1_w, nullptr, fc1_b, nullptr);
    // adapter GEMM2: (32768 x 512) @ (512 x 768), gelu*gate2 + x -> out
    mma_gemm<512, 768, 128, 768, 2><<<dim3(H_/128, M_/128), 256, SMEM_BIG>>>(nullptr, fc2_w, out, fc2_b, x);
}

// round 6
// speedup vs baseline: 2.8357x; 1.0003x over previous
#include <cuda_runtime.h>
#include <math.h>
#include <cstdint>

#define B_ 256
#define S_ 128
#define H_ 768
#define A_ 512
#define N_ 10
#define C_ 3
#define K_ 3
#define M_ (B_*S_)   // 32768

// ---------------- scratch (static device globals; no allocation) ----------------
__device__ float g_W2[H_*32];                 // sem weights rearranged: [h][j], j=n*3+c (30 valid, 2 zero)
__device__ float g_sem[(size_t)M_*30];        // semantic linear out, layout j = n*3+c
__device__ float g_vote[(size_t)K_*M_*C_];    // vote (K,M,C) contiguous; h view = flat reinterpretation
__device__ float g_h2[(size_t)M_*H_];         // x + gated capsule output
__device__ float g_a1[(size_t)M_*A_];         // adapter hidden
__device__ float g_gate1[A_];
__device__ float g_gate2[H_];
__device__ float g_gl[H_];
__device__ int   g_t;

// ---------------- helpers ----------------
__device__ __forceinline__ uint32_t smem_u32(const void* p){
    uint32_t a;
    asm("{ .reg .u64 t; cvta.to.shared.u64 t, %1; cvt.u32.u64 %0, t; }" : "=r"(a) : "l"(p));
    return a;
}
__device__ __forceinline__ void cp_async16(uint32_t smem_addr, const void* gptr){
    asm volatile("cp.async.cg.shared.global [%0], [%1], 16;" :: "r"(smem_addr), "l"(gptr));
}
__device__ __forceinline__ void mma_tf32(float* c, const uint32_t* a, const uint32_t* b){
    asm volatile("mma.sync.aligned.m16n8k8.row.col.f32.tf32.tf32.f32 "
        "{%0,%1,%2,%3}, {%4,%5,%6,%7}, {%8,%9}, {%0,%1,%2,%3};"
        : "+f"(c[0]), "+f"(c[1]), "+f"(c[2]), "+f"(c[3])
        : "r"(a[0]), "r"(a[1]), "r"(a[2]), "r"(a[3]), "r"(b[0]), "r"(b[1]));
}

__device__ __forceinline__ int decode_int(const void* p){
    int v = *(const int*)p;
    if (v >= -1000000 && v <= 1000000) return v;
    return (int)__int_as_float(v);
}
__device__ __forceinline__ float decode_float(const void* p){
    int v = *(const int*)p;
    if (v >= -1000000 && v <= 1000000) return (float)v;
    return __int_as_float(v);
}
__device__ __forceinline__ float sigmoidf_(float x){ return 1.f/(1.f+expf(-x)); }
__device__ __forceinline__ float gelu_exact(float x){
    return 0.5f*x*(1.f+erff(x*0.70710678118654752f));
}

// ---------------- K0: decode scalars, precompute HAT gates ----------------
__global__ void prep_kernel(const void* tptr, const void* sptr,
                            const float* __restrict__ efc1,
                            const float* __restrict__ efc2,
                            const float* __restrict__ elarger){
    __shared__ int st; __shared__ float ssf;
    if (threadIdx.x == 0){
        int t = decode_int(tptr);
        float sf = decode_float(sptr);
        st = t; ssf = sf; g_t = t;
    }
    __syncthreads();
    int t = st; float sf = ssf;
    int i = threadIdx.x;
    if (i < A_) g_gate1[i] = sigmoidf_(sf*efc1[t*A_+i]);
    if (i < H_){
        g_gate2[i] = sigmoidf_(sf*efc2[t*H_+i]);
        g_gl[i]    = sigmoidf_(sf*elarger[t*H_+i]);
    }
}

// ---------------- K0b: rearrange sem_w (N,H,C) -> W2[h][j], j=n*3+c, padded to 32 ----------------
__global__ void w2_kernel(const float* __restrict__ sem_w){
    int idx = blockIdx.x*blockDim.x + threadIdx.x;
    if (idx >= H_*32) return;
    int h = idx >> 5, j = idx & 31;
    float v = 0.f;
    if (j < 30){ int n = j/3, c = j - 3*n; v = sem_w[(n*H_+h)*C_ + c]; }
    g_W2[idx] = v;
}

// ---------------- tf32 mma.sync GEMM, 3-stage cp.async ring, fused epilogues ----------------
// EPI 0: g_sem = x @ g_W2 + sem_b              (BN=32, NOUT=30)
// EPI 1: g_a1  = gelu(g_h2 @ fc1_w + b)*g1     (BN=128, NOUT=512)
// EPI 2: out   = x + gelu(g_a1 @ fc2_w + b)*g2 (BN=128, NOUT=768)
template<int KTOT, int NOUT, int BN, int LDB, int EPI>
__global__ void __launch_bounds__(256) mma_gemm(
    const float* __restrict__ Ain, const float* __restrict__ Bglob,
    float* __restrict__ Cout,
    const float* __restrict__ bias, const float* __restrict__ resid)
{
    constexpr int BM = 128, BK = 16;
    constexpr int SA = BK + 4;        // 20 floats: conflict-free A frag loads
    constexpr int SB = BN + 8;        // conflict-free B frag loads
    constexpr int NKC = KTOT / BK;
    constexpr int WN  = BN / 2;       // warp n-extent (4x2 warp grid)
    constexpr int NTW = WN / 8;       // n-tiles per warp
    constexpr int AB = BM*SA;         // floats per A stage
    constexpr int BB = BK*SB;         // floats per B stage

    extern __shared__ float sm[];
    float* Asm = sm;
    float* Bsm = sm + 3*AB;
    const uint32_t sbase = smem_u32(sm);
    const uint32_t bbase = sbase + 3*AB*4;

    const int tid = threadIdx.x, lane = tid & 31, wid = tid >> 5;
    const int warp_m = wid & 3, warp_n = wid >> 2;
    const int m0 = blockIdx.y * BM, n0 = blockIdx.x * BN;

    const float* Ap = (EPI==0) ? Ain : (EPI==1) ? (const float*)g_h2 : (const float*)g_a1;
    const float* Bp = (EPI==0) ? (const float*)g_W2 : Bglob;

    float acc[2][NTW][4];
    #pragma unroll
    for (int mt=0;mt<2;mt++)
        #pragma unroll
        for (int nt=0;nt<NTW;nt++)
            #pragma unroll
            for (int e=0;e<4;e++) acc[mt][nt][e]=0.f;

    auto loadAB = [&](int kc){
        const int st = kc % 3;
        const float* srcA = Ap + (size_t)m0*KTOT + kc*BK;
        #pragma unroll
        for (int i=0;i<2;i++){
            int q = tid + 256*i;            // 512 chunks of 16B
            int r = q >> 2, s = q & 3;
            cp_async16(sbase + (st*AB + r*SA + s*4)*4, srcA + (size_t)r*KTOT + s*4);
        }
        const float* srcB = Bp + (size_t)(kc*BK)*LDB + n0;
        if (BN == 128){
            #pragma unroll
            for (int i=0;i<2;i++){
                int q = tid + 256*i;        // 512 chunks
                int r = q >> 5, s = q & 31;
                cp_async16(bbase + (st*BB + r*SB + s*4)*4, srcB + (size_t)r*LDB + s*4);
            }
        } else {
            if (tid < 128){
                int r = tid >> 3, s = tid & 7;   // 16 rows x 8 chunks
                cp_async16(bbase + (st*BB + r*SB + s*4)*4, srcB + (size_t)r*LDB + s*4);
            }
        }
        asm volatile("cp.async.commit_group;" ::: "memory");
    };

    auto compute = [&](int st){
        const float* As = Asm + st*AB;
        const float* Bs = Bsm + st*BB;
        #pragma unroll
        for (int ks=0; ks<2; ks++){
            uint32_t af[2][4];
            const int ar = warp_m*32 + (lane>>2);
            const int ac = ks*8 + (lane&3);
            #pragma unroll
            for (int mt=0;mt<2;mt++){
                af[mt][0] = __float_as_uint(As[(ar+mt*16  )*SA + ac  ]);
                af[mt][1] = __float_as_uint(As[(ar+mt*16+8)*SA + ac  ]);
                af[mt][2] = __float_as_uint(As[(ar+mt*16  )*SA + ac+4]);
                af[mt][3] = __float_as_uint(As[(ar+mt*16+8)*SA + ac+4]);
            }
            uint32_t bf[NTW][2];
            const int br = ks*8 + (lane&3);
            const int bc = warp_n*WN + (lane>>2);
            #pragma unroll
            for (int nt=0;nt<NTW;nt++){
                bf[nt][0] = __float_as_uint(Bs[(br  )*SB + bc + nt*8]);
                bf[nt][1] = __float_as_uint(Bs[(br+4)*SB + bc + nt*8]);
            }
            #pragma unroll
            for (int mt=0;mt<2;mt++)
                #pragma unroll
                for (int nt=0;nt<NTW;nt++)
                    mma_tf32(acc[mt][nt], af[mt], bf[nt]);
        }
    };

    // prologue: stage 0 and 1
    loadAB(0);
    if (NKC > 1) loadAB(1);

    for (int kc = 0; kc < NKC; kc++){
        if (kc + 1 < NKC) asm volatile("cp.async.wait_group 1;" ::: "memory");
        else              asm volatile("cp.async.wait_group 0;" ::: "memory");
        __syncthreads();
        if (kc + 2 < NKC) loadAB(kc + 2);
        compute(kc % 3);
    }

    // ---------------- epilogue ----------------
    const float* gate = (EPI==1) ? (const float*)g_gate1 : (const float*)g_gate2;
    #pragma unroll
    for (int mt=0;mt<2;mt++){
        #pragma unroll
        for (int nt=0;nt<NTW;nt++){
            int row = m0 + warp_m*32 + mt*16 + (lane>>2);
            int col = n0 + warp_n*WN + nt*8 + (lane&3)*2;
            #pragma unroll
            for (int half=0; half<2; half++){
                int r = row + half*8;
                float v0 = acc[mt][nt][half*2+0];
                float v1 = acc[mt][nt][half*2+1];
                if (EPI == 0){
                    if (col   < 30) Cout[(size_t)r*30 + col  ] = v0 + bias[col];
                    if (col+1 < 30) Cout[(size_t)r*30 + col+1] = v1 + bias[col+1];
                } else {
                    v0 = gelu_exact(v0 + bias[col  ]) * gate[col  ];
                    v1 = gelu_exact(v1 + bias[col+1]) * gate[col+1];
                    size_t o = (size_t)r*NOUT + col;
                    if (EPI == 2){ v0 += resid[o]; v1 += resid[o+1]; }
                    float2 vv = make_float2(v0, v1);
                    *(float2*)((EPI==1 ? (float*)g_a1 : Cout) + o) = vv;
                }
            }
        }
    }
}

// ---------------- K2: squash + dynamic routing (one thread per m) ----------------
__global__ void routing_kernel(const float* __restrict__ route_w){
    __shared__ float ssem[256*30];
    __shared__ float srw[K_*N_*C_*C_];  // 270
    int m0 = blockIdx.x * 256;
    for (int i = threadIdx.x; i < 256*30; i += 256) ssem[i] = g_sem[(size_t)m0*30 + i];
    if (threadIdx.x < 270) srw[threadIdx.x] = route_w[threadIdx.x];
    __syncthreads();
    int t = g_t;
    int m = m0 + threadIdx.x;

    float v[30];
    #pragma unroll
    for (int i=0;i<30;i++) v[i] = ssem[threadIdx.x*30+i];

    float u[30];
    #pragma unroll
    for (int c=0;c<3;c++){
        float sn = 1e-16f;
        #pragma unroll
        for (int n=0;n<10;n++){ float xx = v[n*3+c]; sn += xx*xx; }
        float scale = (sn/(1.f+sn)) * rsqrtf(sn);
        #pragma unroll
        for (int n=0;n<10;n++) u[c*10+n] = v[n*3+c]*scale;
    }

    for (int k=0;k<3;k++){
        float pri[10][3];
        #pragma unroll
        for (int np=0;np<10;np++){
            #pragma unroll
            for (int d=0;d<3;d++){
                float s = 0.f;
                #pragma unroll
                for (int cp=0;cp<3;cp++)
                    s += u[np*3+cp] * srw[((k*10+np)*3+cp)*3+d];
                pri[np][d]=s;
            }
        }
        float logit[10];
        #pragma unroll
        for (int n=0;n<10;n++) logit[n]=0.f;
        float vt0=0.f, vt1=0.f, vt2=0.f;
        #pragma unroll
        for (int it=0; it<3; it++){
            float mx = -1e30f;
            #pragma unroll
            for (int n=0;n<10;n++){ logit[n] = (n<=t)?logit[n]:-10000.f; mx = fmaxf(mx, logit[n]); }
            float p[10]; float sum=0.f;
            #pragma unroll
            for (int n=0;n<10;n++){ p[n]=expf(logit[n]-mx); sum+=p[n]; }
            float inv = 1.f/sum;
            vt0=vt1=vt2=0.f;
            #pragma unroll
            for (int n=0;n<10;n++){
                float w = p[n]*inv;
                vt0 += w*pri[n][0]; vt1 += w*pri[n][1]; vt2 += w*pri[n][2];
            }
            if (it<2){
                float sn = vt0*vt0+vt1*vt1+vt2*vt2+1e-16f;
                float scale = (sn/(1.f+sn))*rsqrtf(sn);
                #pragma unroll
                for (int n=0;n<10;n++)
                    logit[n] += scale*(pri[n][0]*vt0+pri[n][1]*vt1+pri[n][2]*vt2);
            }
        }
        size_t base = ((size_t)k*M_ + m)*3;
        g_vote[base+0]=vt0; g_vote[base+1]=vt1; g_vote[base+2]=vt2;
    }
}

// ---------------- K3: h2 = x + (vote9 @ larger_w + larger_b) * glarger ----------------
__global__ void h2_kernel(const float* __restrict__ X,
                          const float* __restrict__ lw, const float* __restrict__ lb){
    __shared__ float sv[16*9];
    int r0 = blockIdx.x * 16;
    if (threadIdx.x < 144) sv[threadIdx.x] = g_vote[(size_t)r0*9 + threadIdx.x];
    float w[3][9], bb[3], gl[3];
    #pragma unroll
    for (int j=0;j<3;j++){
        int h = threadIdx.x + j*256;
        #pragma unroll
        for (int e=0;e<9;e++) w[j][e] = lw[e*H_ + h];
        bb[j] = lb[h]; gl[j] = g_gl[h];
    }
    __syncthreads();
    for (int r=0;r<16;r++){
        int m = r0 + r;
        float vv[9];
        #pragma unroll
        for (int e=0;e<9;e++) vv[e]=sv[r*9+e];
        #pragma unroll
        for (int j=0;j<3;j++){
            int h = threadIdx.x + j*256;
            float cap = bb[j];
            #pragma unroll
            for (int e=0;e<9;e++) cap += vv[e]*w[j][e];
            g_h2[(size_t)m*H_+h] = X[(size_t)m*H_+h] + cap*gl[j];
        }
    }
}

// ---------------- launch ----------------
extern "C" void kernel_launch(void* const* d_in, const int* in_sizes, int n_in,
                              void* d_out, int out_size){
    const float* x       = (const float*)d_in[0];
    const void*  tptr    = d_in[1];
    const void*  sptr    = d_in[2];
    const float* fc1_w   = (const float*)d_in[3];
    const float* fc1_b   = (const float*)d_in[4];
    const float* fc2_w   = (const float*)d_in[5];
    const float* fc2_b   = (const float*)d_in[6];
    const float* efc1    = (const float*)d_in[7];
    const float* efc2    = (const float*)d_in[8];
    const float* sem_w   = (const float*)d_in[9];
    const float* sem_b   = (const float*)d_in[10];
    const float* route_w = (const float*)d_in[11];
    const float* larger_w= (const float*)d_in[12];
    const float* larger_b= (const float*)d_in[13];
    const float* elarger = (const float*)d_in[14];
    float* out = (float*)d_out;
    (void)in_sizes; (void)n_in; (void)out_size;

    // dynamic smem sizes: 3 stages of (A:128*20 + B:BK*(BN+8)) floats
    const int SMEM_BIG = 3 * (128*20 + 16*136) * 4;   // 56832 B
    const int SMEM_SEM = 3 * (128*20 + 16*40)  * 4;   // 38400 B

    static float* sem_ptr = nullptr;
    if (!sem_ptr){
        cudaGetSymbolAddress((void**)&sem_ptr, g_sem);
        cudaFuncSetAttribute((const void*)mma_gemm<768, 512, 128, 512, 1>,
                             cudaFuncAttributeMaxDynamicSharedMemorySize, SMEM_BIG);
        cudaFuncSetAttribute((const void*)mma_gemm<512, 768, 128, 768, 2>,
                             cudaFuncAttributeMaxDynamicSharedMemorySize, SMEM_BIG);
    }

    prep_kernel<<<1, 768>>>(tptr, sptr, efc1, efc2, elarger);
    w2_kernel<<<(H_*32 + 255)/256, 256>>>(sem_w);

    // sem GEMM (tf32 mma): (32768 x 768) @ (768 x 30)
    mma_gemm<768, 30, 32, 32, 0><<<dim3(1, M_/128), 256, SMEM_SEM>>>(x, nullptr, sem_ptr, sem_b, nullptr);
    routing_kernel<<<M_/256, 256>>>(route_w);
    h2_kernel<<<M_/16, 256>>>(x, larger_w, larger_b);
    // adapter GEMM1: (32768 x 768) @ (768 x 512), gelu*gate1 -> g_a1
    mma_gemm<768, 512, 128, 512, 1><<<dim3(A_/128, M_/128), 256, SMEM_BIG>>>(nullptr, fc1_w, nullptr, fc1_b, nullptr);
    // adapter GEMM2: (32768 x 512) @ (512 x 768), gelu*gate2 + x -> out
    mma_gemm<512, 768, 128, 768, 2><<<dim3(H_/128, M_/128), 256, SMEM_BIG>>>(nullptr, fc2_w, out, fc2_b, x);
}

// round 8
// speedup vs baseline: 3.9411x; 1.3898x over previous
#include <cuda_runtime.h>
#include <cuda_fp16.h>
#include <math.h>
#include <cstdint>

#define B_ 256
#define S_ 128
#define H_ 768
#define A_ 512
#define N_ 10
#define C_ 3
#define K_ 3
#define M_ (B_*S_)   // 32768

// ---------------- scratch (static device globals; no allocation) ----------------
__device__ float  g_W2[H_*32];                 // sem weights rearranged: [h][j], j=n*3+c
__device__ float  g_sem[(size_t)M_*30];        // semantic linear out
__device__ float  g_vote[(size_t)K_*M_*C_];    // vote (K,M,C) contiguous
__device__ __half g_h2h[(size_t)M_*H_];        // half(x + gated capsule output)
__device__ __half g_a1h[(size_t)M_*A_];        // adapter hidden (half)
__device__ __half g_w1h[(size_t)A_*H_];        // fc1_w^T as half [512][768]
__device__ __half g_w2h[(size_t)H_*A_];        // fc2_w^T as half [768][512]
__device__ float  g_gate1[A_];
__device__ float  g_gate2[H_];
__device__ float  g_gl[H_];
__device__ int    g_t;

// ---------------- helpers ----------------
__device__ __forceinline__ uint32_t smem_u32(const void* p){
    uint32_t a;
    asm("{ .reg .u64 t; cvta.to.shared.u64 t, %1; cvt.u32.u64 %0, t; }" : "=r"(a) : "l"(p));
    return a;
}
__device__ __forceinline__ void cp_async16(uint32_t smem_addr, const void* gptr){
    asm volatile("cp.async.cg.shared.global [%0], [%1], 16;" :: "r"(smem_addr), "l"(gptr));
}
__device__ __forceinline__ void mma_tf32(float* c, const uint32_t* a, const uint32_t* b){
    asm volatile("mma.sync.aligned.m16n8k8.row.col.f32.tf32.tf32.f32 "
        "{%0,%1,%2,%3}, {%4,%5,%6,%7}, {%8,%9}, {%0,%1,%2,%3};"
        : "+f"(c[0]), "+f"(c[1]), "+f"(c[2]), "+f"(c[3])
        : "r"(a[0]), "r"(a[1]), "r"(a[2]), "r"(a[3]), "r"(b[0]), "r"(b[1]));
}
__device__ __forceinline__ void mma_f16(float* c, const uint32_t* a, const uint32_t* b){
    asm volatile("mma.sync.aligned.m16n8k16.row.col.f32.f16.f16.f32 "
        "{%0,%1,%2,%3}, {%4,%5,%6,%7}, {%8,%9}, {%0,%1,%2,%3};"
        : "+f"(c[0]), "+f"(c[1]), "+f"(c[2]), "+f"(c[3])
        : "r"(a[0]), "r"(a[1]), "r"(a[2]), "r"(a[3]), "r"(b[0]), "r"(b[1]));
}

__device__ __forceinline__ int decode_int(const void* p){
    int v = *(const int*)p;
    if (v >= -1000000 && v <= 1000000) return v;
    return (int)__int_as_float(v);
}
__device__ __forceinline__ float decode_float(const void* p){
    int v = *(const int*)p;
    if (v >= -1000000 && v <= 1000000) return (float)v;
    return __int_as_float(v);
}
__device__ __forceinline__ float sigmoidf_(float x){ return 1.f/(1.f+expf(-x)); }
__device__ __forceinline__ float gelu_exact(float x){
    return 0.5f*x*(1.f+erff(x*0.70710678118654752f));
}

// ---------------- K0: decode scalars, precompute HAT gates ----------------
__global__ void prep_kernel(const void* tptr, const void* sptr,
                            const float* __restrict__ efc1,
                            const float* __restrict__ efc2,
                            const float* __restrict__ elarger){
    __shared__ int st; __shared__ float ssf;
    if (threadIdx.x == 0){
        int t = decode_int(tptr);
        float sf = decode_float(sptr);
        st = t; ssf = sf; g_t = t;
    }
    __syncthreads();
    int t = st; float sf = ssf;
    int i = threadIdx.x;
    if (i < A_) g_gate1[i] = sigmoidf_(sf*efc1[t*A_+i]);
    if (i < H_){
        g_gate2[i] = sigmoidf_(sf*efc2[t*H_+i]);
        g_gl[i]    = sigmoidf_(sf*elarger[t*H_+i]);
    }
}

// ---------------- K0b: rearrange sem_w (N,H,C) -> W2[h][j], j=n*3+c, padded to 32 ----------------
__global__ void w2_kernel(const float* __restrict__ sem_w){
    int idx = blockIdx.x*blockDim.x + threadIdx.x;
    if (idx >= H_*32) return;
    int h = idx >> 5, j = idx & 31;
    float v = 0.f;
    if (j < 30){ int n = j/3, c = j - 3*n; v = sem_w[(n*H_+h)*C_ + c]; }
    g_W2[idx] = v;
}

// ---------------- weight transpose + fp32->fp16: src[R][Cc] -> dst[Cc][R] half ----------------
__global__ void wconv_kernel(const float* __restrict__ src, __half* __restrict__ dst, int R, int Cc){
    __shared__ float t[32][33];
    int bx = blockIdx.x*32, by = blockIdx.y*32;
    #pragma unroll
    for (int i = 0; i < 32; i += 8)
        t[threadIdx.y+i][threadIdx.x] = src[(size_t)(by+threadIdx.y+i)*Cc + bx+threadIdx.x];
    __syncthreads();
    #pragma unroll
    for (int i = 0; i < 32; i += 8)
        dst[(size_t)(bx+threadIdx.y+i)*R + by+threadIdx.x] = __float2half(t[threadIdx.x][threadIdx.y+i]);
}

// ---------------- tf32 mma.sync GEMM (sem only), 3-stage ----------------
template<int KTOT, int LDB>
__global__ void __launch_bounds__(256) sem_gemm(
    const float* __restrict__ Ain, float* __restrict__ Cout, const float* __restrict__ bias)
{
    constexpr int BM = 128, BK = 16, BN = 32;
    constexpr int SA = BK + 4;
    constexpr int SB = BN + 8;
    constexpr int NKC = KTOT / BK;
    constexpr int WN  = BN / 2;
    constexpr int NTW = WN / 8;
    constexpr int AB = BM*SA;
    constexpr int BB = BK*SB;

    extern __shared__ float sm[];
    float* Asm = sm;
    float* Bsm = sm + 3*AB;
    const uint32_t sbase = smem_u32(sm);
    const uint32_t bbase = sbase + 3*AB*4;

    const int tid = threadIdx.x, lane = tid & 31, wid = tid >> 5;
    const int warp_m = wid & 3, warp_n = wid >> 2;
    const int m0 = blockIdx.y * BM;
    const float* Bp = (const float*)g_W2;

    float acc[2][NTW][4];
    #pragma unroll
    for (int mt=0;mt<2;mt++) for (int nt=0;nt<NTW;nt++) for (int e=0;e<4;e++) acc[mt][nt][e]=0.f;

    auto loadAB = [&](int kc){
        const int st = kc % 3;
        const float* srcA = Ain + (size_t)m0*KTOT + kc*BK;
        #pragma unroll
        for (int i=0;i<2;i++){
            int q = tid + 256*i;
            int r = q >> 2, s = q & 3;
            cp_async16(sbase + (st*AB + r*SA + s*4)*4, srcA + (size_t)r*KTOT + s*4);
        }
        const float* srcB = Bp + (size_t)(kc*BK)*LDB;
        if (tid < 128){
            int r = tid >> 3, s = tid & 7;
            cp_async16(bbase + (st*BB + r*SB + s*4)*4, srcB + (size_t)r*LDB + s*4);
        }
        asm volatile("cp.async.commit_group;" ::: "memory");
    };
    auto compute = [&](int st){
        const float* As = Asm + st*AB;
        const float* Bs = Bsm + st*BB;
        #pragma unroll
        for (int ks=0; ks<2; ks++){
            uint32_t af[2][4];
            const int ar = warp_m*32 + (lane>>2);
            const int ac = ks*8 + (lane&3);
            #pragma unroll
            for (int mt=0;mt<2;mt++){
                af[mt][0] = __float_as_uint(As[(ar+mt*16  )*SA + ac  ]);
                af[mt][1] = __float_as_uint(As[(ar+mt*16+8)*SA + ac  ]);
                af[mt][2] = __float_as_uint(As[(ar+mt*16  )*SA + ac+4]);
                af[mt][3] = __float_as_uint(As[(ar+mt*16+8)*SA + ac+4]);
            }
            uint32_t bf[NTW][2];
            const int br = ks*8 + (lane&3);
            const int bc = warp_n*WN + (lane>>2);
            #pragma unroll
            for (int nt=0;nt<NTW;nt++){
                bf[nt][0] = __float_as_uint(Bs[(br  )*SB + bc + nt*8]);
                bf[nt][1] = __float_as_uint(Bs[(br+4)*SB + bc + nt*8]);
            }
            #pragma unroll
            for (int mt=0;mt<2;mt++) for (int nt=0;nt<NTW;nt++) mma_tf32(acc[mt][nt], af[mt], bf[nt]);
        }
    };

    loadAB(0);
    if (NKC > 1) loadAB(1);
    for (int kc = 0; kc < NKC; kc++){
        if (kc + 1 < NKC) asm volatile("cp.async.wait_group 1;" ::: "memory");
        else              asm volatile("cp.async.wait_group 0;" ::: "memory");
        __syncthreads();
        if (kc + 2 < NKC) loadAB(kc + 2);
        compute(kc % 3);
    }

    #pragma unroll
    for (int mt=0;mt<2;mt++){
        #pragma unroll
        for (int nt=0;nt<NTW;nt++){
            int row = m0 + warp_m*32 + mt*16 + (lane>>2);
            int col = warp_n*WN + nt*8 + (lane&3)*2;
            #pragma unroll
            for (int half=0; half<2; half++){
                int r = row + half*8;
                if (col   < 30) Cout[(size_t)r*30 + col  ] = acc[mt][nt][half*2+0] + bias[col];
                if (col+1 < 30) Cout[(size_t)r*30 + col+1] = acc[mt][nt][half*2+1] + bias[col+1];
            }
        }
    }
}

// ---------------- fp16 mma.sync GEMM, 3-stage, fused epilogues ----------------
// EPI 1: g_a1h = half(gelu(g_h2h @ w1 + b)*g1)      (NOUT=512)
// EPI 2: out   = x + gelu(g_a1h @ w2 + b)*g2 (fp32) (NOUT=768)
// A: [M][KTOT] half row-major. B: [N][KTOT] half (n-major rows of k).
template<int KTOT, int NOUT, int EPI>
__global__ void __launch_bounds__(256) hgemm(
    float* __restrict__ Cout, const float* __restrict__ bias, const float* __restrict__ resid)
{
    constexpr int BM = 128, BN = 128, BK = 32;       // halves per k-chunk
    constexpr int SW = 20;                            // words per row (16 data + 4 pad)
    constexpr int NKC = KTOT / BK;
    constexpr int WN  = 64;                           // warp n-extent (4x2 warps)
    constexpr int NTW = 8;
    constexpr int AW = BM*SW;                         // words per A stage
    constexpr int BW = BN*SW;                         // words per B stage

    extern __shared__ uint32_t smw[];
    const uint32_t sbase = smem_u32(smw);
    const uint32_t bbase = sbase + 3*AW*4;

    const int tid = threadIdx.x, lane = tid & 31, wid = tid >> 5;
    const int warp_m = wid & 3, warp_n = wid >> 2;
    const int m0 = blockIdx.y * BM, n0 = blockIdx.x * BN;

    const __half* Ap = (EPI==1) ? (const __half*)g_h2h : (const __half*)g_a1h;
    const __half* Bp = (EPI==1) ? (const __half*)g_w1h : (const __half*)g_w2h;

    float acc[2][NTW][4];
    #pragma unroll
    for (int mt=0;mt<2;mt++) for (int nt=0;nt<NTW;nt++) for (int e=0;e<4;e++) acc[mt][nt][e]=0.f;

    auto loadAB = [&](int kc){
        const int st = kc % 3;
        // A: 128 rows x 32 halves = 4 x 16B per row -> 512 chunks
        const __half* srcA = Ap + (size_t)m0*KTOT + kc*BK;
        #pragma unroll
        for (int i=0;i<2;i++){
            int q = tid + 256*i;
            int r = q >> 2, s = q & 3;
            cp_async16(sbase + (st*AW + r*SW + s*4)*4, srcA + (size_t)r*KTOT + s*8);
        }
        // B: 128 n-rows x 32 halves
        const __half* srcB = Bp + (size_t)n0*KTOT + kc*BK;
        #pragma unroll
        for (int i=0;i<2;i++){
            int q = tid + 256*i;
            int r = q >> 2, s = q & 3;
            cp_async16(bbase + (st*BW + r*SW + s*4)*4, srcB + (size_t)r*KTOT + s*8);
        }
        asm volatile("cp.async.commit_group;" ::: "memory");
    };

    auto compute = [&](int stg){
        const uint32_t* As = smw + stg*AW;
        const uint32_t* Bs = smw + 3*AW + stg*BW;
        #pragma unroll
        for (int ks=0; ks<2; ks++){
            uint32_t af[2][4];
            const int ar = warp_m*32 + (lane>>2);
            const int aw = (lane&3) + ks*8;
            #pragma unroll
            for (int mt=0;mt<2;mt++){
                const uint32_t* r0 = As + (ar+mt*16)*SW;
                const uint32_t* r8 = As + (ar+mt*16+8)*SW;
                af[mt][0] = r0[aw];
                af[mt][1] = r8[aw];
                af[mt][2] = r0[aw+4];
                af[mt][3] = r8[aw+4];
            }
            uint32_t bf[NTW][2];
            const int bw = (lane&3) + ks*8;
            const int bc = warp_n*WN + (lane>>2);
            #pragma unroll
            for (int nt=0;nt<NTW;nt++){
                const uint32_t* rn = Bs + (bc+nt*8)*SW;
                bf[nt][0] = rn[bw];
                bf[nt][1] = rn[bw+4];
            }
            #pragma unroll
            for (int mt=0;mt<2;mt++) for (int nt=0;nt<NTW;nt++) mma_f16(acc[mt][nt], af[mt], bf[nt]);
        }
    };

    loadAB(0);
    loadAB(1);
    for (int kc = 0; kc < NKC; kc++){
        if (kc + 1 < NKC) asm volatile("cp.async.wait_group 1;" ::: "memory");
        else              asm volatile("cp.async.wait_group 0;" ::: "memory");
        __syncthreads();
        if (kc + 2 < NKC) loadAB(kc + 2);
        compute(kc % 3);
    }

    // ---------------- epilogue ----------------
    const float* gate = (EPI==1) ? (const float*)g_gate1 : (const float*)g_gate2;
    #pragma unroll
    for (int mt=0;mt<2;mt++){
        #pragma unroll
        for (int nt=0;nt<NTW;nt++){
            int row = m0 + warp_m*32 + mt*16 + (lane>>2);
            int col = n0 + warp_n*WN + nt*8 + (lane&3)*2;
            float b0 = bias[col], b1 = bias[col+1];
            float gt0 = gate[col], gt1 = gate[col+1];
            #pragma unroll
            for (int half=0; half<2; half++){
                int r = row + half*8;
                float v0 = gelu_exact(acc[mt][nt][half*2+0] + b0) * gt0;
                float v1 = gelu_exact(acc[mt][nt][half*2+1] + b1) * gt1;
                size_t o = (size_t)r*NOUT + col;
                if (EPI == 1){
                    *(__half2*)((__half*)g_a1h + o) = __floats2half2_rn(v0, v1);
                } else {
                    float2 vv = make_float2(v0 + resid[o], v1 + resid[o+1]);
                    *(float2*)(Cout + o) = vv;
                }
            }
        }
    }
}

// ---------------- K2: squash + dynamic routing (one thread per m) ----------------
__global__ void routing_kernel(const float* __restrict__ route_w){
    __shared__ float ssem[256*30];
    __shared__ float srw[K_*N_*C_*C_];  // 270
    int m0 = blockIdx.x * 256;
    for (int i = threadIdx.x; i < 256*30; i += 256) ssem[i] = g_sem[(size_t)m0*30 + i];
    if (threadIdx.x < 270) srw[threadIdx.x] = route_w[threadIdx.x];
    __syncthreads();
    int t = g_t;
    int m = m0 + threadIdx.x;

    float v[30];
    #pragma unroll
    for (int i=0;i<30;i++) v[i] = ssem[threadIdx.x*30+i];

    float u[30];
    #pragma unroll
    for (int c=0;c<3;c++){
        float sn = 1e-16f;
        #pragma unroll
        for (int n=0;n<10;n++){ float xx = v[n*3+c]; sn += xx*xx; }
        float scale = (sn/(1.f+sn)) * rsqrtf(sn);
        #pragma unroll
        for (int n=0;n<10;n++) u[c*10+n] = v[n*3+c]*scale;
    }

    for (int k=0;k<3;k++){
        float pri[10][3];
        #pragma unroll
        for (int np=0;np<10;np++){
            #pragma unroll
            for (int d=0;d<3;d++){
                float s = 0.f;
                #pragma unroll
                for (int cp=0;cp<3;cp++)
                    s += u[np*3+cp] * srw[((k*10+np)*3+cp)*3+d];
                pri[np][d]=s;
            }
        }
        float logit[10];
        #pragma unroll
        for (int n=0;n<10;n++) logit[n]=0.f;
        float vt0=0.f, vt1=0.f, vt2=0.f;
        #pragma unroll
        for (int it=0; it<3; it++){
            float mx = -1e30f;
            #pragma unroll
            for (int n=0;n<10;n++){ logit[n] = (n<=t)?logit[n]:-10000.f; mx = fmaxf(mx, logit[n]); }
            float p[10]; float sum=0.f;
            #pragma unroll
            for (int n=0;n<10;n++){ p[n]=expf(logit[n]-mx); sum+=p[n]; }
            float inv = 1.f/sum;
            vt0=vt1=vt2=0.f;
            #pragma unroll
            for (int n=0;n<10;n++){
                float w = p[n]*inv;
                vt0 += w*pri[n][0]; vt1 += w*pri[n][1]; vt2 += w*pri[n][2];
            }
            if (it<2){
                float sn = vt0*vt0+vt1*vt1+vt2*vt2+1e-16f;
                float scale = (sn/(1.f+sn))*rsqrtf(sn);
                #pragma unroll
                for (int n=0;n<10;n++)
                    logit[n] += scale*(pri[n][0]*vt0+pri[n][1]*vt1+pri[n][2]*vt2);
            }
        }
        size_t base = ((size_t)k*M_ + m)*3;
        g_vote[base+0]=vt0; g_vote[base+1]=vt1; g_vote[base+2]=vt2;
    }
}

// ---------------- K3: h2h = half(x + (vote9 @ larger_w + larger_b) * glarger) ----------------
__global__ void h2_kernel(const float* __restrict__ X,
                          const float* __restrict__ lw, const float* __restrict__ lb){
    __shared__ float sv[16*9];
    int r0 = blockIdx.x * 16;
    if (threadIdx.x < 144) sv[threadIdx.x] = g_vote[(size_t)r0*9 + threadIdx.x];
    float w[3][9], bb[3], gl[3];
    #pragma unroll
    for (int j=0;j<3;j++){
        int h = threadIdx.x + j*256;
        #pragma unroll
        for (int e=0;e<9;e++) w[j][e] = lw[e*H_ + h];
        bb[j] = lb[h]; gl[j] = g_gl[h];
    }
    __syncthreads();
    for (int r=0;r<16;r++){
        int m = r0 + r;
        float vv[9];
        #pragma unroll
        for (int e=0;e<9;e++) vv[e]=sv[r*9+e];
        #pragma unroll
        for (int j=0;j<3;j++){
            int h = threadIdx.x + j*256;
            float cap = bb[j];
            #pragma unroll
            for (int e=0;e<9;e++) cap += vv[e]*w[j][e];
            g_h2h[(size_t)m*H_+h] = __float2half(X[(size_t)m*H_+h] + cap*gl[j]);
        }
    }
}

// ---------------- launch ----------------
extern "C" void kernel_launch(void* const* d_in, const int* in_sizes, int n_in,
                              void* d_out, int out_size){
    const float* x       = (const float*)d_in[0];
    const void*  tptr    = d_in[1];
    const void*  sptr    = d_in[2];
    const float* fc1_w   = (const float*)d_in[3];
    const float* fc1_b   = (const float*)d_in[4];
    const float* fc2_w   = (const float*)d_in[5];
    const float* fc2_b   = (const float*)d_in[6];
    const float* efc1    = (const float*)d_in[7];
    const float* efc2    = (const float*)d_in[8];
    const float* sem_w   = (const float*)d_in[9];
    const float* sem_b   = (const float*)d_in[10];
    const float* route_w = (const float*)d_in[11];
    const float* larger_w= (const float*)d_in[12];
    const float* larger_b= (const float*)d_in[13];
    const float* elarger = (const float*)d_in[14];
    float* out = (float*)d_out;
    (void)in_sizes; (void)n_in; (void)out_size;

    const int SMEM_SEM = 3 * (128*20 + 16*40) * 4;        // 38400 B
    const int SMEM_HG  = 3 * (128*20 + 128*20) * 4;       // 61440 B

    static float*  sem_ptr = nullptr;
    static __half* w1h_ptr = nullptr;
    static __half* w2h_ptr = nullptr;
    if (!sem_ptr){
        cudaGetSymbolAddress((void**)&sem_ptr, g_sem);
        cudaGetSymbolAddress((void**)&w1h_ptr, g_w1h);
        cudaGetSymbolAddress((void**)&w2h_ptr, g_w2h);
        cudaFuncSetAttribute((const void*)hgemm<768, 512, 1>,
                             cudaFuncAttributeMaxDynamicSharedMemorySize, SMEM_HG);
        cudaFuncSetAttribute((const void*)hgemm<512, 768, 2>,
                             cudaFuncAttributeMaxDynamicSharedMemorySize, SMEM_HG);
    }

    prep_kernel<<<1, 768>>>(tptr, sptr, efc1, efc2, elarger);
    w2_kernel<<<(H_*32 + 255)/256, 256>>>(sem_w);
    wconv_kernel<<<dim3(A_/32, H_/32), dim3(32,8)>>>(fc1_w, w1h_ptr, H_, A_);  // -> [512][768]
    wconv_kernel<<<dim3(H_/32, A_/32), dim3(32,8)>>>(fc2_w, w2h_ptr, A_, H_);  // -> [768][512]

    // sem GEMM (tf32): (32768 x 768) @ (768 x 30)
    sem_gemm<768, 32><<<dim3(1, M_/128), 256, SMEM_SEM>>>(x, sem_ptr, sem_b);
    routing_kernel<<<M_/256, 256>>>(route_w);
    h2_kernel<<<M_/16, 256>>>(x, larger_w, larger_b);
    // adapter GEMM1 (fp16): (32768 x 768) @ (768 x 512) -> g_a1h
    hgemm<768, 512, 1><<<dim3(A_/128, M_/128), 256, SMEM_HG>>>(nullptr, fc1_b, nullptr);
    // adapter GEMM2 (fp16): (32768 x 512) @ (512 x 768) + x -> out
    hgemm<512, 768, 2><<<dim3(H_/128, M_/128), 256, SMEM_HG>>>(out, fc2_b, x);
}